// round 1
// baseline (speedup 1.0000x reference)
#include <cuda_runtime.h>
#include <math.h>

#define H       128
#define NNODES  50000
#define NEDGES  600000
#define NTYPES  9          // NUM_EDGE_TYPES + 1 rows in edge_embed
#define TM      64
#define TN      128
#define GEMM_THREADS 256
#define GEMM_SMEM ((TM*H + H*(TN+1)) * sizeof(float))   // As + Bs(pitch 129)

// ---------------- scratch (static device globals; no runtime alloc) ----------
__device__ float g_hW [NNODES * H];        // h @ W_msg^T + b_msg
__device__ float g_msg[NNODES * H];        // segment-summed messages
__device__ float g_gi [NNODES * 3 * H];    // msgs @ W_ih^T + b_ih
__device__ float g_gh [NNODES * 3 * H];    // h    @ W_hh^T + b_hh
__device__ int   g_deg [NNODES];
__device__ int   g_off [NNODES + 1];
__device__ int   g_cur [NNODES];
__device__ int   g_perm[NEDGES];

// ---------------- tiny helpers ----------------
__global__ void zero_deg_kernel() {
    int i = blockIdx.x * blockDim.x + threadIdx.x;
    if (i < NNODES) g_deg[i] = 0;
}

__global__ void count_kernel(const int* __restrict__ edge_index) {
    int e = blockIdx.x * blockDim.x + threadIdx.x;
    if (e < NEDGES) {
        int d = edge_index[NEDGES + e];   // dst row
        atomicAdd(&g_deg[d], 1);
    }
}

// single-block exclusive scan over degrees -> offsets (+ cursor copy)
__global__ void scan_kernel() {
    __shared__ int sums[1024];
    const int CH = (NNODES + 1023) / 1024;   // 49
    int tid  = threadIdx.x;
    int base = tid * CH;
    int s = 0;
    for (int i = 0; i < CH; i++) {
        int idx = base + i;
        if (idx < NNODES) s += g_deg[idx];
    }
    sums[tid] = s;
    __syncthreads();
    // Hillis-Steele inclusive scan
    for (int off = 1; off < 1024; off <<= 1) {
        int v = (tid >= off) ? sums[tid - off] : 0;
        __syncthreads();
        sums[tid] += v;
        __syncthreads();
    }
    int prefix = (tid == 0) ? 0 : sums[tid - 1];
    for (int i = 0; i < CH; i++) {
        int idx = base + i;
        if (idx < NNODES) {
            g_off[idx] = prefix;
            g_cur[idx] = prefix;
            prefix += g_deg[idx];
        }
    }
    if (tid == 1023) g_off[NNODES] = sums[1023];
}

__global__ void scatter_kernel(const int* __restrict__ edge_index) {
    int e = blockIdx.x * blockDim.x + threadIdx.x;
    if (e < NEDGES) {
        int d = edge_index[NEDGES + e];
        int pos = atomicAdd(&g_cur[d], 1);
        g_perm[pos] = e;
    }
}

// ---------------- GEMM: C[M,N] = A[M,128] @ B[N,128]^T + bias[N] -------------
__global__ __launch_bounds__(GEMM_THREADS)
void gemm_bias(const float* __restrict__ A, const float* __restrict__ B,
               const float* __restrict__ bias, float* __restrict__ C,
               int M, int N) {
    extern __shared__ float sm[];
    float* As = sm;                // [TM][128]
    float* Bs = sm + TM * H;       // [128][TN+1]  (pitch 129, conflict-free)

    const int m0  = blockIdx.x * TM;
    const int n0  = blockIdx.y * TN;
    const int tid = threadIdx.x;

    // load A tile (float4, coalesced)
    for (int i = tid; i < TM * (H / 4); i += GEMM_THREADS) {
        int r  = i >> 5;           // /32
        int c4 = i & 31;
        int gm = m0 + r;
        float4 v = make_float4(0.f, 0.f, 0.f, 0.f);
        if (gm < M) v = *(const float4*)(A + (size_t)gm * H + c4 * 4);
        *(float4*)(As + r * H + c4 * 4) = v;
    }
    // load B tile transposed: Bs[k][n] = B[n0+n][k]
    for (int i = tid; i < TN * H; i += GEMM_THREADS) {
        int n = i >> 7;            // /128
        int k = i & 127;
        Bs[k * (TN + 1) + n] = B[(size_t)(n0 + n) * H + k];
    }
    __syncthreads();

    const int lane = tid & 31;
    const int mg   = tid >> 5;     // 0..7, 8 rows each

    float acc[8][4];
    #pragma unroll
    for (int q = 0; q < 4; q++) {
        float b = bias[n0 + lane + 32 * q];
        #pragma unroll
        for (int i = 0; i < 8; i++) acc[i][q] = b;
    }

    #pragma unroll 4
    for (int k = 0; k < H; k++) {
        float b0 = Bs[k * (TN + 1) + lane];
        float b1 = Bs[k * (TN + 1) + lane + 32];
        float b2 = Bs[k * (TN + 1) + lane + 64];
        float b3 = Bs[k * (TN + 1) + lane + 96];
        #pragma unroll
        for (int i = 0; i < 8; i++) {
            float a = As[(mg * 8 + i) * H + k];   // broadcast
            acc[i][0] = fmaf(a, b0, acc[i][0]);
            acc[i][1] = fmaf(a, b1, acc[i][1]);
            acc[i][2] = fmaf(a, b2, acc[i][2]);
            acc[i][3] = fmaf(a, b3, acc[i][3]);
        }
    }

    #pragma unroll
    for (int i = 0; i < 8; i++) {
        int gm = m0 + mg * 8 + i;
        if (gm < M) {
            #pragma unroll
            for (int q = 0; q < 4; q++)
                C[(size_t)gm * N + n0 + lane + 32 * q] = acc[i][q];
        }
    }
}

// ---------------- aggregate: warp per node, float4 per lane ------------------
__global__ void aggregate_kernel(const int* __restrict__ edge_index,
                                 const int* __restrict__ etype,
                                 const float* __restrict__ emb) {
    int warp = (blockIdx.x * blockDim.x + threadIdx.x) >> 5;
    int lane = threadIdx.x & 31;
    if (warp >= NNODES) return;
    int s0 = g_off[warp];
    int s1 = g_off[warp + 1];
    float4 acc = make_float4(0.f, 0.f, 0.f, 0.f);
    for (int i = s0; i < s1; i++) {
        int e = g_perm[i];
        int s = edge_index[e];            // src
        int t = etype[e];
        t = min(max(t, 0), NTYPES - 1);
        float4 hv = *((const float4*)(g_hW + (size_t)s * H) + lane);
        float4 ev = *((const float4*)(emb  + (size_t)t * H) + lane);
        acc.x += hv.x + ev.x;
        acc.y += hv.y + ev.y;
        acc.z += hv.z + ev.z;
        acc.w += hv.w + ev.w;
    }
    *((float4*)(g_msg + (size_t)warp * H) + lane) = acc;
}

// ---------------- fused GRU gates --------------------------------------------
__global__ void gates_kernel(const float* __restrict__ h, float* __restrict__ out) {
    int idx = blockIdx.x * blockDim.x + threadIdx.x;
    if (idx >= NNODES * H) return;
    int n = idx >> 7;
    int j = idx & 127;
    size_t b = (size_t)n * 3 * H;
    float ir = g_gi[b + j],       hr = g_gh[b + j];
    float iz = g_gi[b + H + j],   hz = g_gh[b + H + j];
    float in_ = g_gi[b + 2*H + j], hn = g_gh[b + 2*H + j];
    float r = 1.f / (1.f + __expf(-(ir + hr)));
    float z = 1.f / (1.f + __expf(-(iz + hz)));
    float nn = tanhf(in_ + r * hn);
    out[idx] = (1.f - z) * nn + z * h[idx];
}

// ---------------- launch ------------------------------------------------------
extern "C" void kernel_launch(void* const* d_in, const int* in_sizes, int n_in,
                              void* d_out, int out_size) {
    const float* h     = (const float*)d_in[0];
    const int*   eidx  = (const int*)  d_in[1];   // [2, E]
    const int*   etype = (const int*)  d_in[2];
    const float* W_msg = (const float*)d_in[4];
    const float* b_msg = (const float*)d_in[5];
    const float* emb   = (const float*)d_in[6];
    const float* W_ih  = (const float*)d_in[7];
    const float* W_hh  = (const float*)d_in[8];
    const float* b_ih  = (const float*)d_in[9];
    const float* b_hh  = (const float*)d_in[10];
    float* out = (float*)d_out;

    float *hW, *msg, *gi, *gh;
    cudaGetSymbolAddress((void**)&hW,  g_hW);
    cudaGetSymbolAddress((void**)&msg, g_msg);
    cudaGetSymbolAddress((void**)&gi,  g_gi);
    cudaGetSymbolAddress((void**)&gh,  g_gh);

    cudaFuncSetAttribute(gemm_bias, cudaFuncAttributeMaxDynamicSharedMemorySize,
                         (int)GEMM_SMEM);

    const int MTILES = (NNODES + TM - 1) / TM;   // 782

    zero_deg_kernel<<<(NNODES + 255) / 256, 256>>>();
    gemm_bias<<<dim3(MTILES, 1), GEMM_THREADS, GEMM_SMEM>>>(h, W_msg, b_msg, hW,
                                                            NNODES, H);
    count_kernel  <<<(NEDGES + 255) / 256, 256>>>(eidx);
    scan_kernel   <<<1, 1024>>>();
    scatter_kernel<<<(NEDGES + 255) / 256, 256>>>(eidx);
    aggregate_kernel<<<(NNODES * 32 + 255) / 256, 256>>>(eidx, etype, emb);
    gemm_bias<<<dim3(MTILES, 3), GEMM_THREADS, GEMM_SMEM>>>(msg, W_ih, b_ih, gi,
                                                            NNODES, 3 * H);
    gemm_bias<<<dim3(MTILES, 3), GEMM_THREADS, GEMM_SMEM>>>(h, W_hh, b_hh, gh,
                                                            NNODES, 3 * H);
    gates_kernel<<<(NNODES * H + 255) / 256, 256>>>(h, out);
}